// round 1
// baseline (speedup 1.0000x reference)
#include <cuda_runtime.h>
#include <cuda_bf16.h>
#include <math.h>

#define N 4096
#define D 256
#define BM 128
#define BN 128
#define BK 16

__device__ float g_norm[N * D];
__device__ int   g_lab[N];
__device__ float g_tot[N];
__device__ float g_pos[N];
__device__ double g_loss_sum;
__device__ unsigned long long g_cnt;
__device__ int g_is64;

// Detect whether labels buffer is int64 (high words all zero) or int32.
__global__ void k_detect(const int* __restrict__ lab32) {
    int t = threadIdx.x;
    int nz = 0;
    for (int idx = t; idx < N / 2; idx += 256)
        nz |= (lab32[2 * idx + 1] != 0);
    __shared__ int s_nz;
    if (t == 0) s_nz = 0;
    __syncthreads();
    if (nz) atomicOr(&s_nz, 1);
    __syncthreads();
    if (t == 0) g_is64 = (s_nz == 0) ? 1 : 0;
}

// Row-normalize + label convert + zero accumulators (re-zeroed every replay).
__global__ void k_norm(const float* __restrict__ x, const void* __restrict__ labels) {
    int row = blockIdx.x;
    int t = threadIdx.x;          // 256 threads == D
    float v = x[row * D + t];
    float sq = v * v;
    #pragma unroll
    for (int o = 16; o > 0; o >>= 1) sq += __shfl_down_sync(0xffffffffu, sq, o);
    __shared__ float wsum[8];
    if ((t & 31) == 0) wsum[t >> 5] = sq;
    __syncthreads();
    float s = 0.f;
    #pragma unroll
    for (int w = 0; w < 8; w++) s += wsum[w];
    float denom = fmaxf(sqrtf(s), 1e-12f);
    g_norm[row * D + t] = v / denom;
    if (t == 0) {
        int lv;
        if (g_is64) lv = (int)((const long long*)labels)[row];
        else        lv = ((const int*)labels)[row];
        g_lab[row] = lv;
        g_tot[row] = 0.f;
        g_pos[row] = 0.f;
        if (row == 0) { g_loss_sum = 0.0; g_cnt = 0ull; }
    }
}

// Tiled fp32 "GEMM" over sim = norm @ norm^T with fused exp + row reductions.
// Block: 128x128 tile, 256 threads, 8x8 micro-tile per thread.
__global__ __launch_bounds__(256) void k_gemm() {
    __shared__ float As[BK][BM];
    __shared__ float Bs[BK][BN];
    int tid = threadIdx.x;
    int tx = tid & 15, ty = tid >> 4;
    int iBase = blockIdx.y * BM;
    int jBase = blockIdx.x * BN;

    float acc[8][8];
    #pragma unroll
    for (int m = 0; m < 8; m++)
        #pragma unroll
        for (int n = 0; n < 8; n++) acc[m][n] = 0.f;

    for (int k0 = 0; k0 < D; k0 += BK) {
        #pragma unroll
        for (int r = 0; r < 2; r++) {
            int f = tid + r * 256;      // 0..511
            int row = f >> 2;           // 0..127
            int cf = f & 3;             // which float4 within the 16-wide K slab
            float4 va = *(const float4*)&g_norm[(iBase + row) * D + k0 + cf * 4];
            As[cf * 4 + 0][row] = va.x; As[cf * 4 + 1][row] = va.y;
            As[cf * 4 + 2][row] = va.z; As[cf * 4 + 3][row] = va.w;
            float4 vb = *(const float4*)&g_norm[(jBase + row) * D + k0 + cf * 4];
            Bs[cf * 4 + 0][row] = vb.x; Bs[cf * 4 + 1][row] = vb.y;
            Bs[cf * 4 + 2][row] = vb.z; Bs[cf * 4 + 3][row] = vb.w;
        }
        __syncthreads();
        #pragma unroll
        for (int k = 0; k < BK; k++) {
            float a[8], b[8];
            *(float4*)&a[0] = *(const float4*)&As[k][ty * 8];
            *(float4*)&a[4] = *(const float4*)&As[k][ty * 8 + 4];
            *(float4*)&b[0] = *(const float4*)&Bs[k][tx * 8];
            *(float4*)&b[4] = *(const float4*)&Bs[k][tx * 8 + 4];
            #pragma unroll
            for (int m = 0; m < 8; m++)
                #pragma unroll
                for (int n = 0; n < 8; n++)
                    acc[m][n] += a[m] * b[n];
        }
        __syncthreads();
    }

    // Epilogue: e = exp(2*s) (diag excluded), reduce tot/pos per global row.
    int lj[8];
    #pragma unroll
    for (int n = 0; n < 8; n++) lj[n] = g_lab[jBase + tx * 8 + n];

    #pragma unroll
    for (int m = 0; m < 8; m++) {
        int gi = iBase + ty * 8 + m;
        int li = g_lab[gi];
        float tot = 0.f, pos = 0.f;
        #pragma unroll
        for (int n = 0; n < 8; n++) {
            int gj = jBase + tx * 8 + n;
            if (gi != gj) {
                float e = __expf(2.0f * acc[m][n]);
                tot += e;
                if (li == lj[n]) pos += e;
            }
        }
        // reduce across the 16 tx lanes (same ty => same rows); width=16 segments
        #pragma unroll
        for (int o = 8; o > 0; o >>= 1) {
            tot += __shfl_down_sync(0xffffffffu, tot, o, 16);
            pos += __shfl_down_sync(0xffffffffu, pos, o, 16);
        }
        if (tx == 0) {
            atomicAdd(&g_tot[gi], tot);
            atomicAdd(&g_pos[gi], pos);
        }
    }
}

// Recompute the ~8 positive dots per row, accumulate loss sum + pair count.
__global__ void k_loss() {
    int i = blockIdx.x;
    int t = threadIdx.x;
    __shared__ float ni[D];
    __shared__ int labi_s;
    ni[t] = g_norm[i * D + t];
    if (t == 0) labi_s = g_lab[i];
    __syncthreads();
    int labi = labi_s;
    float negi = g_tot[i] - g_pos[i];

    double lsum = 0.0;
    int cnt = 0;
    for (int j = t; j < N; j += 256) {
        if (j != i && g_lab[j] == labi) {
            const float* nj = g_norm + j * D;
            float s = 0.f;
            #pragma unroll 8
            for (int k = 0; k < D; k++) s += ni[k] * __ldg(&nj[k]);
            float e = __expf(2.0f * s);
            lsum += (double)(logf(e + negi) - 2.0f * s);
            cnt++;
        }
    }
    #pragma unroll
    for (int o = 16; o > 0; o >>= 1) {
        lsum += __shfl_down_sync(0xffffffffu, lsum, o);
        cnt  += __shfl_down_sync(0xffffffffu, cnt, o);
    }
    __shared__ double sd[8];
    __shared__ int si[8];
    if ((t & 31) == 0) { sd[t >> 5] = lsum; si[t >> 5] = cnt; }
    __syncthreads();
    if (t == 0) {
        double L = 0.0; int C = 0;
        #pragma unroll
        for (int w = 0; w < 8; w++) { L += sd[w]; C += si[w]; }
        if (C > 0) {
            atomicAdd(&g_loss_sum, L);
            atomicAdd(&g_cnt, (unsigned long long)C);
        }
    }
}

__global__ void k_final(float* __restrict__ out) {
    out[0] = (float)(g_loss_sum / (double)g_cnt);
}

extern "C" void kernel_launch(void* const* d_in, const int* in_sizes, int n_in,
                              void* d_out, int out_size) {
    const float* x = (const float*)d_in[0];
    const void* labels = d_in[1];

    k_detect<<<1, 256>>>((const int*)labels);
    k_norm<<<N, 256>>>(x, labels);
    dim3 g(N / BN, N / BM);
    k_gemm<<<g, 256>>>();
    k_loss<<<N, 256>>>();
    k_final<<<1, 1>>>((float*)d_out);
}

// round 3
// speedup vs baseline: 3.7553x; 3.7553x over previous
#include <cuda_runtime.h>
#include <cuda_bf16.h>
#include <math.h>
#include <cstdint>

#define N 4096
#define D 256
#define PAIR_CAP (1u << 22)

// ---------------- device globals (scratch; no runtime alloc) ----------------
__device__ __align__(16) float          g_norm[N * D];
__device__ __align__(16) __nv_bfloat16  g_normh[N * D];
__device__ int    g_lab[N];
__device__ float  g_tot[N];
__device__ float  g_pos[N];
__device__ double g_loss_sum;
__device__ unsigned g_paircnt;
__device__ unsigned g_pairs[PAIR_CAP];
__device__ int    g_is64;

// ---------------- smem layout for k_gemm ----------------
// A/B rows: 256 bf16 + 8 bf16 pad = 528 bytes (16B-aligned, bank-conflict-free)
#define ROWB 528
#define SMEM_A    0
#define SMEM_B    (128 * ROWB)
#define SMEM_LABI (2 * 128 * ROWB)
#define SMEM_LABJ (SMEM_LABI + 512)
#define SMEM_TOTAL (SMEM_LABJ + 512)

__device__ __forceinline__ uint32_t smem_u32(const void* p) {
    uint32_t a;
    asm("{ .reg .u64 t; cvta.to.shared.u64 t, %1; cvt.u32.u64 %0, t; }" : "=r"(a) : "l"(p));
    return a;
}

#define CP16(dst, src) \
    asm volatile("cp.async.cg.shared.global [%0], [%1], 16;" :: "r"(dst), "l"(src) : "memory")
#define CP_COMMIT() asm volatile("cp.async.commit_group;" ::: "memory")
#define CP_WAIT(n)  asm volatile("cp.async.wait_group %0;" :: "n"(n) : "memory")

#define LDSM4(r, a) \
    asm volatile("ldmatrix.sync.aligned.m8n8.x4.shared.b16 {%0,%1,%2,%3}, [%4];" \
        : "=r"((r)[0]), "=r"((r)[1]), "=r"((r)[2]), "=r"((r)[3]) : "r"(a))
#define LDSM4T(r, a) \
    asm volatile("ldmatrix.sync.aligned.m8n8.x4.trans.shared.b16 {%0,%1,%2,%3}, [%4];" \
        : "=r"((r)[0]), "=r"((r)[1]), "=r"((r)[2]), "=r"((r)[3]) : "r"(a))

#define MMA16816(d, a, b0_, b1_) \
    asm volatile("mma.sync.aligned.m16n8k16.row.col.f32.bf16.bf16.f32 " \
        "{%0,%1,%2,%3}, {%4,%5,%6,%7}, {%8,%9}, {%0,%1,%2,%3};" \
        : "+f"((d)[0]), "+f"((d)[1]), "+f"((d)[2]), "+f"((d)[3]) \
        : "r"((a)[0]), "r"((a)[1]), "r"((a)[2]), "r"((a)[3]), "r"(b0_), "r"(b1_))

// ---------------- kernels ----------------
__global__ void k_detect(const int* __restrict__ lab32) {
    int t = threadIdx.x;
    int nz = 0;
    for (int idx = t; idx < N / 2; idx += 256)
        nz |= (lab32[2 * idx + 1] != 0);
    __shared__ int s_nz;
    if (t == 0) s_nz = 0;
    __syncthreads();
    if (nz) atomicOr(&s_nz, 1);
    __syncthreads();
    if (t == 0) g_is64 = (s_nz == 0) ? 1 : 0;
}

__global__ void k_norm(const float* __restrict__ x, const void* __restrict__ labels) {
    int row = blockIdx.x;
    int t = threadIdx.x;  // 256 == D
    float v = x[row * D + t];
    float sq = v * v;
    #pragma unroll
    for (int o = 16; o > 0; o >>= 1) sq += __shfl_down_sync(0xffffffffu, sq, o);
    __shared__ float wsum[8];
    if ((t & 31) == 0) wsum[t >> 5] = sq;
    __syncthreads();
    float s = 0.f;
    #pragma unroll
    for (int w = 0; w < 8; w++) s += wsum[w];
    float denom = fmaxf(sqrtf(s), 1e-12f);
    float nv = v / denom;
    g_norm[row * D + t] = nv;
    g_normh[row * D + t] = __float2bfloat16_rn(nv);
    if (t == 0) {
        int lv;
        if (g_is64) lv = (int)((const long long*)labels)[row];
        else        lv = ((const int*)labels)[row];
        g_lab[row] = lv;
        g_tot[row] = 0.f;
        g_pos[row] = 0.f;
        if (row == 0) { g_loss_sum = 0.0; g_paircnt = 0u; }
    }
}

// mma.sync bf16 GEMM over sim = norm @ norm^T with fused exp + row tot/pos +
// positive-pair list. 128x128 tile per CTA, 8 warps (4 in M x 2 in N),
// warp tile 32x64 = 2 m16-tiles x 8 n8-tiles. Full K=256 in smem, cp.async
// double-half pipeline.
__global__ __launch_bounds__(256, 1) void k_gemm() {
    extern __shared__ char smem[];
    const int tid = threadIdx.x, wid = tid >> 5, l = tid & 31;
    const int wm = wid & 3, wn = wid >> 2;
    const int iBase = blockIdx.y * 128;
    const int jBase = blockIdx.x * 128;
    const uint32_t sb = smem_u32(smem);

    int* labi = (int*)(smem + SMEM_LABI);
    int* labj = (int*)(smem + SMEM_LABJ);
    if (tid < 128) labi[tid] = g_lab[iBase + tid];
    else           labj[tid - 128] = g_lab[jBase + tid - 128];

    // Async fill: two K-halves, each 128 rows x 128 bf16 (16 x 16B chunks/row)
    #pragma unroll
    for (int h = 0; h < 2; h++) {
        #pragma unroll
        for (int it = 0; it < 8; it++) {
            int g = tid + it * 256;        // 0..2047
            int row = g >> 4;              // 0..127
            int c = g & 15;                // 16B chunk within half
            uint32_t da = sb + SMEM_A + row * ROWB + h * 256 + c * 16;
            const void* sa = &g_normh[(size_t)(iBase + row) * D + h * 128 + c * 8];
            CP16(da, sa);
            uint32_t db = sb + SMEM_B + row * ROWB + h * 256 + c * 16;
            const void* sbp = &g_normh[(size_t)(jBase + row) * D + h * 128 + c * 8];
            CP16(db, sbp);
        }
        CP_COMMIT();
    }

    float acc[2][8][4];
    #pragma unroll
    for (int mt = 0; mt < 2; mt++)
        #pragma unroll
        for (int nt = 0; nt < 8; nt++)
            #pragma unroll
            for (int e = 0; e < 4; e++) acc[mt][nt][e] = 0.f;

    // Per-lane ldmatrix base addresses.
    // A (non-trans, x4): lanes 0-15 rows 0-15 @k0, lanes 16-31 rows 0-15 @k0+8
    const uint32_t aoff = sb + SMEM_A + (uint32_t)(wm * 32 + (l & 15)) * ROWB + (uint32_t)((l >> 4) * 16);
    // B (trans, x4): lanes{0-7,8-15,16-23,24-31} -> (n0-7,k0),(n0-7,k0+8),(n8-15,k0),(n8-15,k0+8)
    const uint32_t boff = sb + SMEM_B + (uint32_t)(wn * 64 + (l & 7) + ((l & 16) ? 8 : 0)) * ROWB
                        + (uint32_t)(((l >> 3) & 1) * 16);

    CP_WAIT(1);
    __syncthreads();

    #pragma unroll
    for (int ks = 0; ks < 16; ks++) {
        if (ks == 8) {
            CP_WAIT(0);
            __syncthreads();
        }
        uint32_t A0[4], A1[4];
        LDSM4(A0, aoff + ks * 32);
        LDSM4(A1, aoff + 16 * ROWB + ks * 32);
        #pragma unroll
        for (int p = 0; p < 4; p++) {
            uint32_t Bt[4];
            LDSM4T(Bt, boff + p * 16 * ROWB + ks * 32);
            MMA16816(acc[0][2 * p],     A0, Bt[0], Bt[1]);
            MMA16816(acc[0][2 * p + 1], A0, Bt[2], Bt[3]);
            MMA16816(acc[1][2 * p],     A1, Bt[0], Bt[1]);
            MMA16816(acc[1][2 * p + 1], A1, Bt[2], Bt[3]);
        }
    }

    // Epilogue: exp(2s), per-row tot/pos (+pair list). Thread covers 4 rows x 16 cols.
    #pragma unroll
    for (int rh = 0; rh < 4; rh++) {
        const int mt = rh >> 1, half = rh & 1;
        const int row_local = wm * 32 + mt * 16 + half * 8 + (l >> 2);
        const int gi = iBase + row_local;
        const int li = labi[row_local];
        float tot = 0.f, pos = 0.f;
        unsigned pmask = 0u;
        #pragma unroll
        for (int nt = 0; nt < 8; nt++) {
            #pragma unroll
            for (int e = 0; e < 2; e++) {
                int col_local = wn * 64 + nt * 8 + (l & 3) * 2 + e;
                float v = acc[mt][nt][half * 2 + e];
                if (gi != jBase + col_local) {
                    float ex = __expf(2.0f * v);
                    tot += ex;
                    if (labj[col_local] == li) { pos += ex; pmask |= 1u << (nt * 2 + e); }
                }
            }
        }
        tot += __shfl_xor_sync(0xffffffffu, tot, 1);
        tot += __shfl_xor_sync(0xffffffffu, tot, 2);
        pos += __shfl_xor_sync(0xffffffffu, pos, 1);
        pos += __shfl_xor_sync(0xffffffffu, pos, 2);
        if ((l & 3) == 0) {
            atomicAdd(&g_tot[gi], tot);
            atomicAdd(&g_pos[gi], pos);
        }
        if (pmask) {
            int np = __popc(pmask);
            unsigned base = atomicAdd(&g_paircnt, (unsigned)np);
            while (pmask) {
                int b = __ffs(pmask) - 1;
                pmask &= pmask - 1;
                int col_local = wn * 64 + (b >> 1) * 8 + (l & 3) * 2 + (b & 1);
                if (base < PAIR_CAP)
                    g_pairs[base] = ((unsigned)gi << 16) | (unsigned)(jBase + col_local);
                base++;
            }
        }
    }
}

// One warp per positive pair: exact fp32 dot + loss term.
__global__ void k_loss2() {
    unsigned cnt = g_paircnt;
    if (cnt > PAIR_CAP) cnt = PAIR_CAP;
    unsigned gw = (blockIdx.x * blockDim.x + threadIdx.x) >> 5;
    int lane = threadIdx.x & 31;
    unsigned nw = (gridDim.x * blockDim.x) >> 5;
    double acc = 0.0;
    for (unsigned p = gw; p < cnt; p += nw) {
        unsigned pr = g_pairs[p];
        int i = (int)(pr >> 16);
        int j = (int)(pr & 0xffffu);
        const float4* ri = (const float4*)&g_norm[(size_t)i * D];
        const float4* rj = (const float4*)&g_norm[(size_t)j * D];
        float s = 0.f;
        #pragma unroll
        for (int q = 0; q < 2; q++) {
            float4 a = ri[lane * 2 + q];
            float4 b = rj[lane * 2 + q];
            s += a.x * b.x + a.y * b.y + a.z * b.z + a.w * b.w;
        }
        #pragma unroll
        for (int o = 16; o > 0; o >>= 1) s += __shfl_down_sync(0xffffffffu, s, o);
        if (lane == 0) {
            float negi = g_tot[i] - g_pos[i];
            float e = __expf(2.0f * s);
            acc += (double)(logf(e + negi) - 2.0f * s);
        }
    }
    if (lane == 0 && acc != 0.0) atomicAdd(&g_loss_sum, acc);
}

__global__ void k_final(float* __restrict__ out) {
    out[0] = (float)(g_loss_sum / (double)g_paircnt);
}

// ---------------- launch ----------------
extern "C" void kernel_launch(void* const* d_in, const int* in_sizes, int n_in,
                              void* d_out, int out_size) {
    const float* x = (const float*)d_in[0];
    const void* labels = d_in[1];

    static bool attr_done = false;
    if (!attr_done) {
        cudaFuncSetAttribute(k_gemm, cudaFuncAttributeMaxDynamicSharedMemorySize, SMEM_TOTAL);
        attr_done = true;
    }

    k_detect<<<1, 256>>>((const int*)labels);
    k_norm<<<N, 256>>>(x, labels);
    dim3 g(N / 128, N / 128);
    k_gemm<<<g, 256, SMEM_TOTAL>>>();
    k_loss2<<<512, 256>>>();
    k_final<<<1, 1>>>((float*)d_out);
}

// round 4
// speedup vs baseline: 4.7468x; 1.2640x over previous
#include <cuda_runtime.h>
#include <cuda_bf16.h>
#include <math.h>
#include <cstdint>

#define N 4096
#define D 256
#define NB (N / 128)                 // 32 tile-blocks per dim
#define NTILES (NB * (NB + 1) / 2)   // 528 upper-triangle tiles
#define PAIR_CAP (1u << 22)

// ---------------- device globals (scratch; no runtime alloc) ----------------
__device__ __align__(16) __nv_bfloat16  g_normh[N * D];
__device__ int      g_lab[N];
__device__ float    g_tot[N];
__device__ float    g_pos[N];
__device__ double   g_loss_sum;
__device__ unsigned g_paircnt;
__device__ unsigned g_done;
__device__ unsigned g_pair_i[PAIR_CAP];
__device__ float    g_pair_s[PAIR_CAP];
__device__ int      g_is64;

// ---------------- smem layout for k_gemm ----------------
// A/B rows: 256 bf16 + 8 bf16 pad = 528 bytes (16B-aligned, bank-conflict-free)
#define ROWB 528
#define SMEM_A    0
#define SMEM_B    (128 * ROWB)
#define SMEM_LABI (2 * 128 * ROWB)
#define SMEM_LABJ (SMEM_LABI + 512)
#define SMEM_TOTAL (SMEM_LABJ + 512)

__device__ __forceinline__ uint32_t smem_u32(const void* p) {
    uint32_t a;
    asm("{ .reg .u64 t; cvta.to.shared.u64 t, %1; cvt.u32.u64 %0, t; }" : "=r"(a) : "l"(p));
    return a;
}

#define CP16(dst, src) \
    asm volatile("cp.async.cg.shared.global [%0], [%1], 16;" :: "r"(dst), "l"(src) : "memory")
#define CP_COMMIT() asm volatile("cp.async.commit_group;" ::: "memory")
#define CP_WAIT(n)  asm volatile("cp.async.wait_group %0;" :: "n"(n) : "memory")

#define LDSM4(r, a) \
    asm volatile("ldmatrix.sync.aligned.m8n8.x4.shared.b16 {%0,%1,%2,%3}, [%4];" \
        : "=r"((r)[0]), "=r"((r)[1]), "=r"((r)[2]), "=r"((r)[3]) : "r"(a))
#define LDSM4T(r, a) \
    asm volatile("ldmatrix.sync.aligned.m8n8.x4.trans.shared.b16 {%0,%1,%2,%3}, [%4];" \
        : "=r"((r)[0]), "=r"((r)[1]), "=r"((r)[2]), "=r"((r)[3]) : "r"(a))

#define MMA16816(d, a, b0_, b1_) \
    asm volatile("mma.sync.aligned.m16n8k16.row.col.f32.bf16.bf16.f32 " \
        "{%0,%1,%2,%3}, {%4,%5,%6,%7}, {%8,%9}, {%0,%1,%2,%3};" \
        : "+f"((d)[0]), "+f"((d)[1]), "+f"((d)[2]), "+f"((d)[3]) \
        : "r"((a)[0]), "r"((a)[1]), "r"((a)[2]), "r"((a)[3]), "r"(b0_), "r"(b1_))

// ---------------- kernels ----------------
__global__ void k_detect(const int* __restrict__ lab32) {
    int t = threadIdx.x;
    int nz = 0;
    for (int idx = t; idx < N / 2; idx += 256)
        nz |= (lab32[2 * idx + 1] != 0);
    __shared__ int s_nz;
    if (t == 0) s_nz = 0;
    __syncthreads();
    if (nz) atomicOr(&s_nz, 1);
    __syncthreads();
    if (t == 0) g_is64 = (s_nz == 0) ? 1 : 0;
}

__global__ void k_norm(const float* __restrict__ x, const void* __restrict__ labels) {
    int row = blockIdx.x;
    int t = threadIdx.x;  // 256 == D
    float v = x[row * D + t];
    float sq = v * v;
    #pragma unroll
    for (int o = 16; o > 0; o >>= 1) sq += __shfl_down_sync(0xffffffffu, sq, o);
    __shared__ float wsum[8];
    if ((t & 31) == 0) wsum[t >> 5] = sq;
    __syncthreads();
    float s = 0.f;
    #pragma unroll
    for (int w = 0; w < 8; w++) s += wsum[w];
    float denom = fmaxf(sqrtf(s), 1e-12f);
    g_normh[row * D + t] = __float2bfloat16_rn(v / denom);
    if (t == 0) {
        int lv;
        if (g_is64) lv = (int)((const long long*)labels)[row];
        else        lv = ((const int*)labels)[row];
        g_lab[row] = lv;
        g_tot[row] = 0.f;
        g_pos[row] = 0.f;
        if (row == 0) { g_loss_sum = 0.0; g_paircnt = 0u; g_done = 0u; }
    }
}

// mma.sync bf16 GEMM over upper-triangle tiles of sim = norm @ norm^T.
// Fused: exp(2s), row tot/pos, column tot/pos (off-diag tiles), pair list
// with s values. 128x128 tile per CTA, 8 warps (4 M x 2 N), warp tile 32x64.
__global__ __launch_bounds__(256, 1) void k_gemm() {
    extern __shared__ char smem[];
    const int tid = threadIdx.x, wid = tid >> 5, l = tid & 31;
    const int wm = wid & 3, wn = wid >> 2;
    const uint32_t sb = smem_u32(smem);

    // Map linear tile id -> (bi, bj) with bi <= bj.
    int t = blockIdx.x;
    int bi = (int)((65.0 - sqrt(4225.0 - 8.0 * (double)t)) * 0.5);
    // base(r) = 32r - r(r-1)/2
    #pragma unroll 1
    while (32 * (bi + 1) - (bi + 1) * bi / 2 <= t) bi++;
    #pragma unroll 1
    while (32 * bi - bi * (bi - 1) / 2 > t) bi--;
    const int bj = bi + (t - (32 * bi - bi * (bi - 1) / 2));
    const int iBase = bi * 128;
    const int jBase = bj * 128;
    const bool diag = (bi == bj);

    int* labi = (int*)(smem + SMEM_LABI);
    int* labj = (int*)(smem + SMEM_LABJ);
    if (tid < 128) labi[tid] = g_lab[iBase + tid];
    else           labj[tid - 128] = g_lab[jBase + tid - 128];

    // Async fill: two K-halves. Diag tiles reuse A for B.
    #pragma unroll
    for (int h = 0; h < 2; h++) {
        #pragma unroll
        for (int it = 0; it < 8; it++) {
            int g = tid + it * 256;        // 0..2047
            int row = g >> 4;              // 0..127
            int c = g & 15;                // 16B chunk within half
            uint32_t da = sb + SMEM_A + row * ROWB + h * 256 + c * 16;
            CP16(da, &g_normh[(size_t)(iBase + row) * D + h * 128 + c * 8]);
            if (!diag) {
                uint32_t db = sb + SMEM_B + row * ROWB + h * 256 + c * 16;
                CP16(db, &g_normh[(size_t)(jBase + row) * D + h * 128 + c * 8]);
            }
        }
        CP_COMMIT();
    }

    float acc[2][8][4];
    #pragma unroll
    for (int mt = 0; mt < 2; mt++)
        #pragma unroll
        for (int nt = 0; nt < 8; nt++)
            #pragma unroll
            for (int e = 0; e < 4; e++) acc[mt][nt][e] = 0.f;

    const uint32_t aoff = sb + SMEM_A + (uint32_t)(wm * 32 + (l & 15)) * ROWB + (uint32_t)((l >> 4) * 16);
    const uint32_t bbase = diag ? (uint32_t)SMEM_A : (uint32_t)SMEM_B;
    const uint32_t boff = sb + bbase + (uint32_t)(wn * 64 + (l & 7) + ((l & 16) ? 8 : 0)) * ROWB
                        + (uint32_t)(((l >> 3) & 1) * 16);

    CP_WAIT(1);
    __syncthreads();

    #pragma unroll
    for (int ks = 0; ks < 16; ks++) {
        if (ks == 8) {
            CP_WAIT(0);
            __syncthreads();
        }
        uint32_t A0[4], A1[4];
        LDSM4(A0, aoff + ks * 32);
        LDSM4(A1, aoff + 16 * ROWB + ks * 32);
        #pragma unroll
        for (int p = 0; p < 4; p++) {
            uint32_t Bt[4];
            LDSM4T(Bt, boff + p * 16 * ROWB + ks * 32);
            MMA16816(acc[0][2 * p],     A0, Bt[0], Bt[1]);
            MMA16816(acc[0][2 * p + 1], A0, Bt[2], Bt[3]);
            MMA16816(acc[1][2 * p],     A1, Bt[0], Bt[1]);
            MMA16816(acc[1][2 * p + 1], A1, Bt[2], Bt[3]);
        }
    }

    // Epilogue. Per-thread column accumulators for the transpose direction.
    float ctot[16], cpos[16];
    #pragma unroll
    for (int c = 0; c < 16; c++) { ctot[c] = 0.f; cpos[c] = 0.f; }

    #pragma unroll
    for (int mt = 0; mt < 2; mt++) {
        #pragma unroll
        for (int half = 0; half < 2; half++) {
            const int row_local = wm * 32 + mt * 16 + half * 8 + (l >> 2);
            const int gi = iBase + row_local;
            const int li = labi[row_local];
            float tot = 0.f, pos = 0.f;
            #pragma unroll
            for (int nt = 0; nt < 8; nt++) {
                #pragma unroll
                for (int e = 0; e < 2; e++) {
                    const int col_local = wn * 64 + nt * 8 + (l & 3) * 2 + e;
                    const int gj = jBase + col_local;
                    const float s = acc[mt][nt][half * 2 + e];
                    const bool nd = (gi != gj);
                    const float ex = nd ? __expf(2.0f * s) : 0.0f;
                    const bool match = (labj[col_local] == li);
                    const float exm = match ? ex : 0.0f;
                    tot += ex;
                    pos += exm;
                    ctot[nt * 2 + e] += ex;
                    cpos[nt * 2 + e] += exm;
                    if (match && nd) {
                        unsigned base = atomicAdd(&g_paircnt, diag ? 1u : 2u);
                        if (base < PAIR_CAP) { g_pair_i[base] = (unsigned)gi; g_pair_s[base] = s; }
                        if (!diag && base + 1 < PAIR_CAP) { g_pair_i[base + 1] = (unsigned)gj; g_pair_s[base + 1] = s; }
                    }
                }
            }
            tot += __shfl_xor_sync(0xffffffffu, tot, 1);
            tot += __shfl_xor_sync(0xffffffffu, tot, 2);
            pos += __shfl_xor_sync(0xffffffffu, pos, 1);
            pos += __shfl_xor_sync(0xffffffffu, pos, 2);
            if ((l & 3) == 0) {
                atomicAdd(&g_tot[gi], tot);
                atomicAdd(&g_pos[gi], pos);
            }
        }
    }

    // Column (transpose) reductions — only for off-diagonal tiles.
    if (!diag) {
        #pragma unroll
        for (int c = 0; c < 16; c++) {
            #pragma unroll
            for (int m = 4; m <= 16; m <<= 1) {
                ctot[c] += __shfl_xor_sync(0xffffffffu, ctot[c], m);
                cpos[c] += __shfl_xor_sync(0xffffffffu, cpos[c], m);
            }
        }
        if (l < 4) {
            #pragma unroll
            for (int c = 0; c < 16; c++) {
                const int col_local = wn * 64 + (c >> 1) * 8 + l * 2 + (c & 1);
                atomicAdd(&g_tot[jBase + col_local], ctot[c]);
                atomicAdd(&g_pos[jBase + col_local], cpos[c]);
            }
        }
    }
}

// Streaming loss over pair entries (i, s); last block finalizes output.
__global__ void k_loss3(float* __restrict__ out) {
    unsigned cnt = g_paircnt;
    if (cnt > PAIR_CAP) cnt = PAIR_CAP;
    const unsigned gtid = blockIdx.x * blockDim.x + threadIdx.x;
    const unsigned stride = gridDim.x * blockDim.x;
    double acc = 0.0;
    for (unsigned p = gtid; p < cnt; p += stride) {
        unsigned i = g_pair_i[p];
        float s = g_pair_s[p];
        float neg = g_tot[i] - g_pos[i];
        float e = __expf(2.0f * s);
        acc += (double)(logf(e + neg) - 2.0f * s);
    }
    #pragma unroll
    for (int o = 16; o > 0; o >>= 1) acc += __shfl_down_sync(0xffffffffu, acc, o);
    __shared__ double sd[8];
    if ((threadIdx.x & 31) == 0) sd[threadIdx.x >> 5] = acc;
    __syncthreads();
    if (threadIdx.x == 0) {
        double L = 0.0;
        #pragma unroll
        for (int w = 0; w < 8; w++) L += sd[w];
        atomicAdd(&g_loss_sum, L);
        __threadfence();
        unsigned d = atomicAdd(&g_done, 1u);
        if (d == gridDim.x - 1) {
            double total = atomicAdd(&g_loss_sum, 0.0);
            out[0] = (float)(total / (double)g_paircnt);
            g_done = 0u;
        }
    }
}

// ---------------- launch ----------------
extern "C" void kernel_launch(void* const* d_in, const int* in_sizes, int n_in,
                              void* d_out, int out_size) {
    const float* x = (const float*)d_in[0];
    const void* labels = d_in[1];

    static bool attr_done = false;
    if (!attr_done) {
        cudaFuncSetAttribute(k_gemm, cudaFuncAttributeMaxDynamicSharedMemorySize, SMEM_TOTAL);
        attr_done = true;
    }

    k_detect<<<1, 256>>>((const int*)labels);
    k_norm<<<N, 256>>>(x, labels);
    k_gemm<<<NTILES, 256, SMEM_TOTAL>>>();
    k_loss3<<<64, 256>>>((float*)d_out);
}

// round 5
// speedup vs baseline: 5.0787x; 1.0699x over previous
#include <cuda_runtime.h>
#include <cuda_bf16.h>
#include <math.h>
#include <cstdint>

#define N 4096
#define D 256
#define NB (N / 128)                 // 32 tile-blocks per dim
#define NTILES (NB * (NB + 1) / 2)   // 528 upper-triangle tiles
#define PAIR_CAP (1u << 22)

// ---------------- device globals (scratch; no runtime alloc) ----------------
// g_normh rows are stored PRE-SWIZZLED: 16B chunk c of row r lives at chunk
// position (c ^ (r & 7)) within the row's 512 bytes.
__device__ __align__(16) __nv_bfloat16  g_normh[N * D];
__device__ int      g_lab[N];
__device__ float    g_tot[N];
__device__ float    g_pos[N];
__device__ double   g_loss_sum;
__device__ unsigned g_paircnt;
__device__ unsigned g_done;
__device__ unsigned g_pair_i[PAIR_CAP];
__device__ float    g_pair_s[PAIR_CAP];
__device__ int      g_is64;

// ---------------- smem layout for k_gemm (linear 512B rows, data pre-swizzled)
#define SMEM_A    0
#define SMEM_B    65536
#define SMEM_LABI 131072
#define SMEM_LABJ 131584
#define SMEM_MBAR 132096
#define SMEM_TOTAL 132160

__device__ __forceinline__ uint32_t smem_u32(const void* p) {
    uint32_t a;
    asm("{ .reg .u64 t; cvta.to.shared.u64 t, %1; cvt.u32.u64 %0, t; }" : "=r"(a) : "l"(p));
    return a;
}

#define MBAR_INIT(mb, c)  asm volatile("mbarrier.init.shared.b64 [%0], %1;" :: "r"(mb), "r"(c) : "memory")
#define MBAR_EXPECT(mb, tx) asm volatile("mbarrier.arrive.expect_tx.shared.b64 _, [%0], %1;" :: "r"(mb), "r"(tx) : "memory")
#define BULK_LD(dst, src, sz, mb) \
    asm volatile("cp.async.bulk.shared::cta.global.mbarrier::complete_tx::bytes [%0], [%1], %2, [%3];" \
        :: "r"(dst), "l"(src), "r"(sz), "r"(mb) : "memory")

__device__ __forceinline__ void mbar_wait(uint32_t mb, uint32_t parity) {
    uint32_t done;
    asm volatile("{ .reg .pred p; mbarrier.try_wait.parity.acquire.cta.shared::cta.b64 p, [%1], %2; selp.b32 %0, 1, 0, p; }"
                 : "=r"(done) : "r"(mb), "r"(parity) : "memory");
    if (!done) {
        asm volatile("{ .reg .pred P1; W%=: mbarrier.try_wait.parity.acquire.cta.shared::cta.b64 P1, [%0], %1, 0x989680; @P1 bra.uni DN%=; bra.uni W%=; DN%=: }"
                     :: "r"(mb), "r"(parity) : "memory");
    }
}

#define LDSM4(r, a) \
    asm volatile("ldmatrix.sync.aligned.m8n8.x4.shared.b16 {%0,%1,%2,%3}, [%4];" \
        : "=r"((r)[0]), "=r"((r)[1]), "=r"((r)[2]), "=r"((r)[3]) : "r"(a))
#define LDSM4T(r, a) \
    asm volatile("ldmatrix.sync.aligned.m8n8.x4.trans.shared.b16 {%0,%1,%2,%3}, [%4];" \
        : "=r"((r)[0]), "=r"((r)[1]), "=r"((r)[2]), "=r"((r)[3]) : "r"(a))

#define MMA16816(d, a, b0_, b1_) \
    asm volatile("mma.sync.aligned.m16n8k16.row.col.f32.bf16.bf16.f32 " \
        "{%0,%1,%2,%3}, {%4,%5,%6,%7}, {%8,%9}, {%0,%1,%2,%3};" \
        : "+f"((d)[0]), "+f"((d)[1]), "+f"((d)[2]), "+f"((d)[3]) \
        : "r"((a)[0]), "r"((a)[1]), "r"((a)[2]), "r"((a)[3]), "r"(b0_), "r"(b1_))

// ---------------- kernels ----------------
__global__ void k_detect(const int* __restrict__ lab32) {
    int t = threadIdx.x;
    int nz = 0;
    for (int idx = t; idx < N / 2; idx += 256)
        nz |= (lab32[2 * idx + 1] != 0);
    __shared__ int s_nz;
    if (t == 0) s_nz = 0;
    __syncthreads();
    if (nz) atomicOr(&s_nz, 1);
    __syncthreads();
    if (t == 0) g_is64 = (s_nz == 0) ? 1 : 0;
}

__global__ void k_norm(const float* __restrict__ x, const void* __restrict__ labels) {
    int row = blockIdx.x;
    int t = threadIdx.x;  // 256 == D
    float v = x[row * D + t];
    float sq = v * v;
    #pragma unroll
    for (int o = 16; o > 0; o >>= 1) sq += __shfl_down_sync(0xffffffffu, sq, o);
    __shared__ float wsum[8];
    if ((t & 31) == 0) wsum[t >> 5] = sq;
    __syncthreads();
    float s = 0.f;
    #pragma unroll
    for (int w = 0; w < 8; w++) s += wsum[w];
    float denom = fmaxf(sqrtf(s), 1e-12f);
    // pre-swizzled store: chunk c -> c ^ (row & 7)
    int c = t >> 3;
    int cs = c ^ (row & 7);
    g_normh[row * D + cs * 8 + (t & 7)] = __float2bfloat16_rn(v / denom);
    if (t == 0) {
        int lv;
        if (g_is64) lv = (int)((const long long*)labels)[row];
        else        lv = ((const int*)labels)[row];
        g_lab[row] = lv;
        g_tot[row] = 0.f;
        g_pos[row] = 0.f;
        if (row == 0) { g_loss_sum = 0.0; g_paircnt = 0u; g_done = 0u; }
    }
}

// mma.sync bf16 GEMM over upper-triangle tiles of sim = norm @ norm^T.
// Fill via cp.async.bulk (contiguous 64KB per operand, pre-swizzled layout).
__global__ __launch_bounds__(256, 1) void k_gemm() {
    extern __shared__ char smem[];
    const int tid = threadIdx.x, wid = tid >> 5, l = tid & 31;
    const int wm = wid & 3, wn = wid >> 2;
    const uint32_t sb = smem_u32(smem);

    // Map linear tile id -> (bi, bj) with bi <= bj.
    int t = blockIdx.x;
    int bi = (int)((65.0 - sqrt(4225.0 - 8.0 * (double)t)) * 0.5);
    #pragma unroll 1
    while (32 * (bi + 1) - (bi + 1) * bi / 2 <= t) bi++;
    #pragma unroll 1
    while (32 * bi - bi * (bi - 1) / 2 > t) bi--;
    const int bj = bi + (t - (32 * bi - bi * (bi - 1) / 2));
    const int iBase = bi * 128;
    const int jBase = bj * 128;
    const bool diag = (bi == bj);

    if (tid == 0) MBAR_INIT(sb + SMEM_MBAR, 1);
    __syncthreads();
    if (tid == 0) {
        unsigned tx = diag ? 65536u : 131072u;
        MBAR_EXPECT(sb + SMEM_MBAR, tx);
    }
    __syncthreads();
    // 8KB bulk chunks: A by threads 0-7, B by threads 8-15.
    if (tid < 8) {
        BULK_LD(sb + SMEM_A + tid * 8192,
                (const char*)&g_normh[(size_t)iBase * D] + tid * 8192,
                8192u, sb + SMEM_MBAR);
    } else if (!diag && tid < 16) {
        BULK_LD(sb + SMEM_B + (tid - 8) * 8192,
                (const char*)&g_normh[(size_t)jBase * D] + (tid - 8) * 8192,
                8192u, sb + SMEM_MBAR);
    }

    int* labi = (int*)(smem + SMEM_LABI);
    int* labj = (int*)(smem + SMEM_LABJ);
    if (tid < 128) labi[tid] = g_lab[iBase + tid];
    else           labj[tid - 128] = g_lab[jBase + tid - 128];

    float acc[2][8][4];
    #pragma unroll
    for (int mt = 0; mt < 2; mt++)
        #pragma unroll
        for (int nt = 0; nt < 8; nt++)
            #pragma unroll
            for (int e = 0; e < 4; e++) acc[mt][nt][e] = 0.f;

    // Per-lane ldmatrix bases (rows), swizzle XOR applied per-ks.
    const int row_a = wm * 32 + (l & 15);
    const uint32_t abase = sb + SMEM_A + (uint32_t)row_a * 512;
    const int rxa = row_a & 7;
    const int hia = (l >> 4);                  // 0/1 -> +8 in k
    const uint32_t bsp = diag ? (uint32_t)SMEM_A : (uint32_t)SMEM_B;
    const int row_b = wn * 64 + (l & 7) + ((l & 16) ? 8 : 0);
    const uint32_t bbase = sb + bsp + (uint32_t)row_b * 512;
    const int rxb = row_b & 7;                 // invariant under +16 row steps
    const int hib = (l >> 3) & 1;

    mbar_wait(sb + SMEM_MBAR, 0);
    __syncthreads();

    #pragma unroll
    for (int ks = 0; ks < 16; ks++) {
        const uint32_t ka = (uint32_t)(((ks * 2 + hia) ^ rxa) << 4);
        const uint32_t kb = (uint32_t)(((ks * 2 + hib) ^ rxb) << 4);
        uint32_t A0[4], A1[4];
        LDSM4(A0, abase + ka);
        LDSM4(A1, abase + 8192 + ka);          // +16 rows * 512B
        #pragma unroll
        for (int p = 0; p < 4; p++) {
            uint32_t Bt[4];
            LDSM4T(Bt, bbase + (uint32_t)p * 8192 + kb);
            MMA16816(acc[0][2 * p],     A0, Bt[0], Bt[1]);
            MMA16816(acc[0][2 * p + 1], A0, Bt[2], Bt[3]);
            MMA16816(acc[1][2 * p],     A1, Bt[0], Bt[1]);
            MMA16816(acc[1][2 * p + 1], A1, Bt[2], Bt[3]);
        }
    }

    // Epilogue: exp(2s), row tot/pos, column tot/pos (off-diag), pair list.
    float ctot[16], cpos[16];
    #pragma unroll
    for (int c = 0; c < 16; c++) { ctot[c] = 0.f; cpos[c] = 0.f; }

    #pragma unroll
    for (int mt = 0; mt < 2; mt++) {
        #pragma unroll
        for (int half = 0; half < 2; half++) {
            const int row_local = wm * 32 + mt * 16 + half * 8 + (l >> 2);
            const int gi = iBase + row_local;
            const int li = labi[row_local];
            float tot = 0.f, pos = 0.f;
            #pragma unroll
            for (int nt = 0; nt < 8; nt++) {
                #pragma unroll
                for (int e = 0; e < 2; e++) {
                    const int col_local = wn * 64 + nt * 8 + (l & 3) * 2 + e;
                    const int gj = jBase + col_local;
                    const float s = acc[mt][nt][half * 2 + e];
                    const bool nd = (gi != gj);
                    const float ex = nd ? __expf(2.0f * s) : 0.0f;
                    const bool match = (labj[col_local] == li);
                    const float exm = match ? ex : 0.0f;
                    tot += ex;
                    pos += exm;
                    ctot[nt * 2 + e] += ex;
                    cpos[nt * 2 + e] += exm;
                    if (match && nd) {
                        unsigned base = atomicAdd(&g_paircnt, diag ? 1u : 2u);
                        if (base < PAIR_CAP) { g_pair_i[base] = (unsigned)gi; g_pair_s[base] = s; }
                        if (!diag && base + 1 < PAIR_CAP) { g_pair_i[base + 1] = (unsigned)gj; g_pair_s[base + 1] = s; }
                    }
                }
            }
            tot += __shfl_xor_sync(0xffffffffu, tot, 1);
            tot += __shfl_xor_sync(0xffffffffu, tot, 2);
            pos += __shfl_xor_sync(0xffffffffu, pos, 1);
            pos += __shfl_xor_sync(0xffffffffu, pos, 2);
            if ((l & 3) == 0) {
                atomicAdd(&g_tot[gi], tot);
                atomicAdd(&g_pos[gi], pos);
            }
        }
    }

    if (!diag) {
        #pragma unroll
        for (int c = 0; c < 16; c++) {
            #pragma unroll
            for (int m = 4; m <= 16; m <<= 1) {
                ctot[c] += __shfl_xor_sync(0xffffffffu, ctot[c], m);
                cpos[c] += __shfl_xor_sync(0xffffffffu, cpos[c], m);
            }
        }
        if (l < 4) {
            #pragma unroll
            for (int c = 0; c < 16; c++) {
                const int col_local = wn * 64 + (c >> 1) * 8 + l * 2 + (c & 1);
                atomicAdd(&g_tot[jBase + col_local], ctot[c]);
                atomicAdd(&g_pos[jBase + col_local], cpos[c]);
            }
        }
    }
}

// Streaming loss over pair entries (i, s); last block finalizes output.
__global__ void k_loss3(float* __restrict__ out) {
    unsigned cnt = g_paircnt;
    if (cnt > PAIR_CAP) cnt = PAIR_CAP;
    const unsigned gtid = blockIdx.x * blockDim.x + threadIdx.x;
    const unsigned stride = gridDim.x * blockDim.x;
    double acc = 0.0;
    for (unsigned p = gtid; p < cnt; p += stride) {
        unsigned i = g_pair_i[p];
        float s = g_pair_s[p];
        float neg = g_tot[i] - g_pos[i];
        float e = __expf(2.0f * s);
        acc += (double)(logf(e + neg) - 2.0f * s);
    }
    #pragma unroll
    for (int o = 16; o > 0; o >>= 1) acc += __shfl_down_sync(0xffffffffu, acc, o);
    __shared__ double sd[8];
    if ((threadIdx.x & 31) == 0) sd[threadIdx.x >> 5] = acc;
    __syncthreads();
    if (threadIdx.x == 0) {
        double L = 0.0;
        #pragma unroll
        for (int w = 0; w < 8; w++) L += sd[w];
        atomicAdd(&g_loss_sum, L);
        __threadfence();
        unsigned d = atomicAdd(&g_done, 1u);
        if (d == gridDim.x - 1) {
            double total = atomicAdd(&g_loss_sum, 0.0);
            out[0] = (float)(total / (double)g_paircnt);
            g_done = 0u;
        }
    }
}

// ---------------- launch ----------------
extern "C" void kernel_launch(void* const* d_in, const int* in_sizes, int n_in,
                              void* d_out, int out_size) {
    const float* x = (const float*)d_in[0];
    const void* labels = d_in[1];

    static bool attr_done = false;
    if (!attr_done) {
        cudaFuncSetAttribute(k_gemm, cudaFuncAttributeMaxDynamicSharedMemorySize, SMEM_TOTAL);
        attr_done = true;
    }

    k_detect<<<1, 256>>>((const int*)labels);
    k_norm<<<N, 256>>>(x, labels);
    k_gemm<<<NTILES, 256, SMEM_TOTAL>>>();
    k_loss3<<<128, 256>>>((float*)d_out);
}

// round 6
// speedup vs baseline: 5.4899x; 1.0810x over previous
#include <cuda_runtime.h>
#include <cuda_bf16.h>
#include <cuda_fp16.h>
#include <math.h>
#include <cstdint>

#define N 4096
#define D 256
#define NB (N / 128)
#define NTILES (NB * (NB + 1) / 2)   // 528
#define NLAB 512
#define BCAP 64                       // fast-path bucket capacity

// ---------------- device globals ----------------
__device__ __align__(16) __nv_bfloat16  g_normh[N * D]; // rows pre-swizzled: chunk c at c^(row&7)
__device__ int      g_lab[N];
__device__ float    g_tot[N];
__device__ float    g_loss_f;
__device__ unsigned g_cnt;
__device__ unsigned g_done;
__device__ int      g_bstart[NLAB + 1];
__device__ int      g_bidx[N];
__device__ int      g_is64;

// ---------------- smem layout for k_gemm ----------------
#define SMEM_A    0
#define SMEM_B    65536
#define SMEM_MB0  131072
#define SMEM_MB1  131080
#define SMEM_GT   131104

__device__ __forceinline__ uint32_t smem_u32(const void* p) {
    uint32_t a;
    asm("{ .reg .u64 t; cvta.to.shared.u64 t, %1; cvt.u32.u64 %0, t; }" : "=r"(a) : "l"(p));
    return a;
}

#define MBAR_INIT(mb, c)  asm volatile("mbarrier.init.shared.b64 [%0], %1;" :: "r"(mb), "r"(c) : "memory")
#define MBAR_EXPECT(mb, tx) asm volatile("mbarrier.arrive.expect_tx.shared.b64 _, [%0], %1;" :: "r"(mb), "r"(tx) : "memory")
#define BULK_LD(dst, src, sz, mb) \
    asm volatile("cp.async.bulk.shared::cta.global.mbarrier::complete_tx::bytes [%0], [%1], %2, [%3];" \
        :: "r"(dst), "l"(src), "r"(sz), "r"(mb) : "memory")

__device__ __forceinline__ void mbar_wait(uint32_t mb, uint32_t parity) {
    uint32_t done;
    asm volatile("{ .reg .pred p; mbarrier.try_wait.parity.acquire.cta.shared::cta.b64 p, [%1], %2; selp.b32 %0, 1, 0, p; }"
                 : "=r"(done) : "r"(mb), "r"(parity) : "memory");
    if (!done) {
        asm volatile("{ .reg .pred P1; W%=: mbarrier.try_wait.parity.acquire.cta.shared::cta.b64 P1, [%0], %1, 0x989680; @P1 bra.uni DN%=; bra.uni W%=; DN%=: }"
                     :: "r"(mb), "r"(parity) : "memory");
    }
}

#define LDSM4(r, a) \
    asm volatile("ldmatrix.sync.aligned.m8n8.x4.shared.b16 {%0,%1,%2,%3}, [%4];" \
        : "=r"((r)[0]), "=r"((r)[1]), "=r"((r)[2]), "=r"((r)[3]) : "r"(a))
#define LDSM4T(r, a) \
    asm volatile("ldmatrix.sync.aligned.m8n8.x4.trans.shared.b16 {%0,%1,%2,%3}, [%4];" \
        : "=r"((r)[0]), "=r"((r)[1]), "=r"((r)[2]), "=r"((r)[3]) : "r"(a))

#define MMA16816(d, a, b0_, b1_) \
    asm volatile("mma.sync.aligned.m16n8k16.row.col.f32.bf16.bf16.f32 " \
        "{%0,%1,%2,%3}, {%4,%5,%6,%7}, {%8,%9}, {%0,%1,%2,%3};" \
        : "+f"((d)[0]), "+f"((d)[1]), "+f"((d)[2]), "+f"((d)[3]) \
        : "r"((a)[0]), "r"((a)[1]), "r"((a)[2]), "r"((a)[3]), "r"(b0_), "r"(b1_))

// ---------------- kernels ----------------
__global__ void k_detect(const int* __restrict__ lab32) {
    int t = threadIdx.x;
    int nz = 0;
    for (int idx = t; idx < N / 2; idx += 256)
        nz |= (lab32[2 * idx + 1] != 0);
    __shared__ int s_nz;
    if (t == 0) s_nz = 0;
    __syncthreads();
    if (nz) atomicOr(&s_nz, 1);
    __syncthreads();
    if (t == 0) g_is64 = (s_nz == 0) ? 1 : 0;
}

__global__ void k_norm(const float* __restrict__ x, const void* __restrict__ labels) {
    int row = blockIdx.x;
    int t = threadIdx.x;  // 256 == D
    float v = x[row * D + t];
    float sq = v * v;
    #pragma unroll
    for (int o = 16; o > 0; o >>= 1) sq += __shfl_down_sync(0xffffffffu, sq, o);
    __shared__ float wsum[8];
    if ((t & 31) == 0) wsum[t >> 5] = sq;
    __syncthreads();
    float s = 0.f;
    #pragma unroll
    for (int w = 0; w < 8; w++) s += wsum[w];
    float denom = fmaxf(sqrtf(s), 1e-12f);
    int c = t >> 3;
    int cs = c ^ (row & 7);
    g_normh[row * D + cs * 8 + (t & 7)] = __float2bfloat16_rn(v / denom);
    if (t == 0) {
        int lv;
        if (g_is64) lv = (int)((const long long*)labels)[row];
        else        lv = ((const int*)labels)[row];
        g_lab[row] = lv;
        g_tot[row] = 0.f;
    }
}

// Group rows by label: histogram + scan + scatter. One block, 512 threads.
__global__ void k_bucket() {
    __shared__ int cnt[NLAB];
    __shared__ int buf[2][NLAB];
    int t = threadIdx.x;
    cnt[t] = 0;
    if (t == 0) { g_loss_f = 0.f; g_cnt = 0u; g_done = 0u; }
    __syncthreads();
    for (int r = t; r < N; r += NLAB) atomicAdd(&cnt[g_lab[r]], 1);
    __syncthreads();
    // inclusive scan (Hillis-Steele, double buffer)
    buf[0][t] = cnt[t];
    __syncthreads();
    int src = 0;
    #pragma unroll
    for (int o = 1; o < NLAB; o <<= 1) {
        int v = buf[src][t];
        if (t >= o) v += buf[src][t - o];
        buf[1 - src][t] = v;
        src = 1 - src;
        __syncthreads();
    }
    int excl = buf[src][t] - cnt[t];
    g_bstart[t] = excl;
    if (t == NLAB - 1) g_bstart[NLAB] = N;
    cnt[t] = excl;   // reuse as cursor
    __syncthreads();
    for (int r = t; r < N; r += NLAB) {
        int p = atomicAdd(&cnt[g_lab[r]], 1);
        g_bidx[p] = r;
    }
}

// bf16 mma.sync GEMM over upper-triangle tiles: ONLY tot sums (row + column).
__global__ __launch_bounds__(256, 1) void k_gemm() {
    extern __shared__ char smem[];
    const int tid = threadIdx.x, wid = tid >> 5, l = tid & 31;
    const int wm = wid & 3, wn = wid >> 2;
    const uint32_t sb = smem_u32(smem);

    int t = blockIdx.x;
    int bi = (int)((65.0 - sqrt(4225.0 - 8.0 * (double)t)) * 0.5);
    #pragma unroll 1
    while (32 * (bi + 1) - (bi + 1) * bi / 2 <= t) bi++;
    #pragma unroll 1
    while (32 * bi - bi * (bi - 1) / 2 > t) bi--;
    const int bj = bi + (t - (32 * bi - bi * (bi - 1) / 2));
    const int iBase = bi * 128;
    const int jBase = bj * 128;
    const bool diag = (bi == bj);

    if (tid == 0) {
        MBAR_INIT(sb + SMEM_MB0, 1);
        MBAR_INIT(sb + SMEM_MB1, 1);
    }
    __syncthreads();
    if (tid == 0) {
        unsigned tx = diag ? 32768u : 65536u;
        MBAR_EXPECT(sb + SMEM_MB0, tx);
        MBAR_EXPECT(sb + SMEM_MB1, tx);
    }
    __syncthreads();
    // low halves (rows 0-63) -> mb0 ; high halves (rows 64-127) -> mb1
    if (tid < 4) {
        BULK_LD(sb + SMEM_A + tid * 8192,
                (const char*)&g_normh[(size_t)iBase * D] + tid * 8192, 8192u, sb + SMEM_MB0);
    } else if (!diag && tid < 8) {
        BULK_LD(sb + SMEM_B + (tid - 4) * 8192,
                (const char*)&g_normh[(size_t)jBase * D] + (tid - 4) * 8192, 8192u, sb + SMEM_MB0);
    } else if (tid >= 8 && tid < 12) {
        BULK_LD(sb + SMEM_A + 32768 + (tid - 8) * 8192,
                (const char*)&g_normh[(size_t)iBase * D] + 32768 + (tid - 8) * 8192, 8192u, sb + SMEM_MB1);
    } else if (!diag && tid >= 12 && tid < 16) {
        BULK_LD(sb + SMEM_B + 32768 + (tid - 12) * 8192,
                (const char*)&g_normh[(size_t)jBase * D] + 32768 + (tid - 12) * 8192, 8192u, sb + SMEM_MB1);
    }

    float acc[2][8][4];
    #pragma unroll
    for (int mt = 0; mt < 2; mt++)
        #pragma unroll
        for (int nt = 0; nt < 8; nt++)
            #pragma unroll
            for (int e = 0; e < 4; e++) acc[mt][nt][e] = 0.f;

    const int row_a = wm * 32 + (l & 15);
    const uint32_t abase = sb + SMEM_A + (uint32_t)row_a * 512;
    const int rxa = row_a & 7;
    const int hia = (l >> 4);
    const uint32_t bsp = diag ? (uint32_t)SMEM_A : (uint32_t)SMEM_B;
    const int row_b = wn * 64 + (l & 7) + ((l & 16) ? 8 : 0);
    const uint32_t bbase = sb + bsp + (uint32_t)row_b * 512;
    const int rxb = row_b & 7;
    const int hib = (l >> 3) & 1;

    // warp needs: A rows [wm*32,+32), B rows [wn*64,+64)
    mbar_wait(sb + SMEM_MB0, 0);
    if (wm >= 2 || wn == 1) mbar_wait(sb + SMEM_MB1, 0);

    #pragma unroll
    for (int ks = 0; ks < 16; ks++) {
        const uint32_t ka = (uint32_t)(((ks * 2 + hia) ^ rxa) << 4);
        const uint32_t kb = (uint32_t)(((ks * 2 + hib) ^ rxb) << 4);
        uint32_t A0[4], A1[4];
        LDSM4(A0, abase + ka);
        LDSM4(A1, abase + 8192 + ka);
        #pragma unroll
        for (int p = 0; p < 4; p++) {
            uint32_t Bt[4];
            LDSM4T(Bt, bbase + (uint32_t)p * 8192 + kb);
            MMA16816(acc[0][2 * p],     A0, Bt[0], Bt[1]);
            MMA16816(acc[0][2 * p + 1], A0, Bt[2], Bt[3]);
            MMA16816(acc[1][2 * p],     A1, Bt[0], Bt[1]);
            MMA16816(acc[1][2 * p + 1], A1, Bt[2], Bt[3]);
        }
    }

    // Epilogue: exp(2s) via f16x2 EX2; row + column sums only.
    const half2 SC = __float2half2_rn(2.8853900817779268f);   // 2*log2(e)
    half2 ctot2[8];
    #pragma unroll
    for (int nt = 0; nt < 8; nt++) ctot2[nt] = __float2half2_rn(0.f);

    half2 cidx[8];
    if (diag) {
        #pragma unroll
        for (int nt = 0; nt < 8; nt++) {
            float c0 = (float)(wn * 64 + nt * 8 + (l & 3) * 2);
            cidx[nt] = __floats2half2_rn(c0, c0 + 1.0f);
        }
    }

    #pragma unroll
    for (int mt = 0; mt < 2; mt++) {
        #pragma unroll
        for (int half_ = 0; half_ < 2; half_++) {
            const int row_local = wm * 32 + mt * 16 + half_ * 8 + (l >> 2);
            const int gi = iBase + row_local;
            half2 t2 = __float2half2_rn(0.f);
            if (diag) {
                const half2 r2 = __float2half2_rn((float)row_local);
                #pragma unroll
                for (int nt = 0; nt < 8; nt++) {
                    half2 h = __floats2half2_rn(acc[mt][nt][half_ * 2], acc[mt][nt][half_ * 2 + 1]);
                    half2 ex = h2exp2(__hmul2(h, SC));
                    half2 eq = __heq2(cidx[nt], r2);
                    ex = __hsub2(ex, __hmul2(ex, eq));   // zero diagonal element
                    t2 = __hadd2(t2, ex);
                    ctot2[nt] = __hadd2(ctot2[nt], ex);
                }
            } else {
                #pragma unroll
                for (int nt = 0; nt < 8; nt++) {
                    half2 h = __floats2half2_rn(acc[mt][nt][half_ * 2], acc[mt][nt][half_ * 2 + 1]);
                    half2 ex = h2exp2(__hmul2(h, SC));
                    t2 = __hadd2(t2, ex);
                    ctot2[nt] = __hadd2(ctot2[nt], ex);
                }
            }
            float2 f = __half22float2(t2);
            float tt = f.x + f.y;
            tt += __shfl_xor_sync(0xffffffffu, tt, 1);
            tt += __shfl_xor_sync(0xffffffffu, tt, 2);
            if ((l & 3) == 0) atomicAdd(&g_tot[gi], tt);
        }
    }

    if (!diag) {
        #pragma unroll
        for (int nt = 0; nt < 8; nt++) {
            uint32_t v = *(uint32_t*)&ctot2[nt];
            #pragma unroll
            for (int m = 4; m <= 16; m <<= 1) {
                uint32_t o = __shfl_xor_sync(0xffffffffu, v, m);
                half2 hv = *(half2*)&v, ho = *(half2*)&o;
                hv = __hadd2(hv, ho);
                v = *(uint32_t*)&hv;
            }
            if (l < 4) {
                float2 fc = __half22float2(*(half2*)&v);
                int c0 = wn * 64 + nt * 8 + l * 2;
                atomicAdd(&g_tot[jBase + c0], fc.x);
                atomicAdd(&g_tot[jBase + c0 + 1], fc.y);
            }
        }
    }
}

// ---------------- loss: one block per label bucket ----------------
__device__ __forceinline__ void tri_decode(int p, int n, int& a, int& b) {
    a = 0;
    int rem = p;
    while (rem >= n - 1 - a) { rem -= (n - 1 - a); a++; }
    b = a + 1 + rem;
}

// warp dot of two unswizzled smem rows (uint4 per lane = 8 bf16)
__device__ __forceinline__ float warp_dot_smem(const uint4* ra, const uint4* rb, int l) {
    uint4 xa = ra[l], xb = rb[l];
    float s = 0.f;
    const uint32_t* pa = (const uint32_t*)&xa;
    const uint32_t* pb = (const uint32_t*)&xb;
    #pragma unroll
    for (int q = 0; q < 4; q++) {
        float2 fa = __bfloat1622float2(*(const __nv_bfloat162*)&pa[q]);
        float2 fb = __bfloat1622float2(*(const __nv_bfloat162*)&pb[q]);
        s += fa.x * fb.x + fa.y * fb.y;
    }
    #pragma unroll
    for (int o = 16; o > 0; o >>= 1) s += __shfl_xor_sync(0xffffffffu, s, o);
    return s;
}

__device__ __forceinline__ float warp_dot_gmem(int ga, int gb, int l) {
    // chunk l of each row, unswizzled
    const uint4* pa = (const uint4*)&g_normh[(size_t)ga * D + (size_t)((l ^ (ga & 7)) * 8)];
    const uint4* pb = (const uint4*)&g_normh[(size_t)gb * D + (size_t)((l ^ (gb & 7)) * 8)];
    uint4 xa = *pa, xb = *pb;
    float s = 0.f;
    const uint32_t* qa = (const uint32_t*)&xa;
    const uint32_t* qb = (const uint32_t*)&xb;
    #pragma unroll
    for (int q = 0; q < 4; q++) {
        float2 fa = __bfloat1622float2(*(const __nv_bfloat162*)&qa[q]);
        float2 fb = __bfloat1622float2(*(const __nv_bfloat162*)&qb[q]);
        s += fa.x * fb.x + fa.y * fb.y;
    }
    #pragma unroll
    for (int o = 16; o > 0; o >>= 1) s += __shfl_xor_sync(0xffffffffu, s, o);
    return s;
}

#define LSM_ROWS 0
#define LSM_SMAT (BCAP * 32 * 16)                  // 32768
#define LSM_NEG  (LSM_SMAT + BCAP * (BCAP + 1) * 4) // + 16640
#define LSM_IDX  (LSM_NEG + BCAP * 4)
#define LSM_TOTAL (LSM_IDX + BCAP * 4 + 64)

__global__ __launch_bounds__(128) void k_loss4(float* __restrict__ out) {
    extern __shared__ char sm[];
    uint4* rows4 = (uint4*)(sm + LSM_ROWS);            // [BCAP][32]
    float* smat  = (float*)(sm + LSM_SMAT);            // [BCAP][BCAP+1]
    float* sneg  = (float*)(sm + LSM_NEG);
    int*   sidx  = (int*)(sm + LSM_IDX);

    const int L = blockIdx.x;
    const int tid = threadIdx.x, wid = tid >> 5, l = tid & 31;
    const int base = g_bstart[L];
    const int n = g_bstart[L + 1] - base;
    float lsum = 0.f;
    unsigned lcnt = 0;

    if (n >= 2 && n <= BCAP) {
        if (tid < n) sidx[tid] = g_bidx[base + tid];
        __syncthreads();
        // load rows unswizzled: n*32 chunks of 16B
        for (int idx = tid; idx < n * 32; idx += 128) {
            int a = idx >> 5, c = idx & 31;
            int gr = sidx[a];
            rows4[a * 32 + c] = *(const uint4*)&g_normh[(size_t)gr * D + (size_t)((c ^ (gr & 7)) * 8)];
        }
        __syncthreads();
        const int np = n * (n - 1) / 2;
        for (int p = wid; p < np; p += 4) {
            int a, b;
            tri_decode(p, n, a, b);
            float s = warp_dot_smem(&rows4[a * 32], &rows4[b * 32], l);
            if (l == 0) {
                smat[a * (BCAP + 1) + b] = s;
                smat[b * (BCAP + 1) + a] = s;
            }
        }
        __syncthreads();
        if (tid < n) {
            float pos = 0.f;
            for (int b = 0; b < n; b++)
                if (b != tid) pos += __expf(2.0f * smat[tid * (BCAP + 1) + b]);
            sneg[tid] = g_tot[sidx[tid]] - pos;
        }
        __syncthreads();
        for (int p = tid; p < np; p += 128) {
            int a, b;
            tri_decode(p, n, a, b);
            float s = smat[a * (BCAP + 1) + b];
            float e = __expf(2.0f * s);
            lsum += logf(e + sneg[a]) + logf(e + sneg[b]) - 4.0f * s;
        }
        lcnt = (tid == 0) ? (unsigned)(2 * np) : 0u;
    } else if (n > BCAP) {
        // slow path (insurance; not expected for this dataset)
        for (int a = wid; a < n; a += 4) {
            int ga = g_bidx[base + a];
            float pos = 0.f;
            for (int b = 0; b < n; b++) {
                if (b == a) continue;
                float s = warp_dot_gmem(ga, g_bidx[base + b], l);
                pos += __expf(2.0f * s);
            }
            float neg = g_tot[ga] - pos;
            float part = 0.f;
            for (int b = 0; b < n; b++) {
                if (b == a) continue;
                float s = warp_dot_gmem(ga, g_bidx[base + b], l);
                float e = __expf(2.0f * s);
                part += logf(e + neg) - 2.0f * s;
            }
            if (l == 0) { lsum += part; lcnt += (unsigned)(n - 1); }
        }
    }

    // block reduce lsum
    #pragma unroll
    for (int o = 16; o > 0; o >>= 1) lsum += __shfl_down_sync(0xffffffffu, lsum, o);
    __shared__ float sred[4];
    __shared__ unsigned scnt[4];
    unsigned wcnt = lcnt;
    #pragma unroll
    for (int o = 16; o > 0; o >>= 1) wcnt += __shfl_down_sync(0xffffffffu, wcnt, o);
    if (l == 0) { sred[wid] = lsum; scnt[wid] = wcnt; }
    __syncthreads();
    if (tid == 0) {
        float Ls = sred[0] + sred[1] + sred[2] + sred[3];
        unsigned C = scnt[0] + scnt[1] + scnt[2] + scnt[3];
        if (Ls != 0.f) atomicAdd(&g_loss_f, Ls);
        if (C) atomicAdd(&g_cnt, C);
        __threadfence();
        unsigned d = atomicAdd(&g_done, 1u);
        if (d == gridDim.x - 1) {
            float total = atomicAdd(&g_loss_f, 0.f);
            unsigned cc = atomicAdd(&g_cnt, 0u);
            out[0] = total / (float)cc;
        }
    }
}

// ---------------- launch ----------------
extern "C" void kernel_launch(void* const* d_in, const int* in_sizes, int n_in,
                              void* d_out, int out_size) {
    const float* x = (const float*)d_in[0];
    const void* labels = d_in[1];

    static bool attr_done = false;
    if (!attr_done) {
        cudaFuncSetAttribute(k_gemm, cudaFuncAttributeMaxDynamicSharedMemorySize, SMEM_GT);
        cudaFuncSetAttribute(k_loss4, cudaFuncAttributeMaxDynamicSharedMemorySize, LSM_TOTAL);
        attr_done = true;
    }

    k_detect<<<1, 256>>>((const int*)labels);
    k_norm<<<N, 256>>>(x, labels);
    k_bucket<<<1, NLAB>>>();
    k_gemm<<<NTILES, 256, SMEM_GT>>>();
    k_loss4<<<NLAB, 128, LSM_TOTAL>>>((float*)d_out);
}

// round 7
// speedup vs baseline: 6.1775x; 1.1253x over previous
#include <cuda_runtime.h>
#include <cuda_bf16.h>
#include <cuda_fp16.h>
#include <math.h>
#include <cstdint>

#define N 4096
#define D 256
#define NB (N / 128)
#define NTILES (NB * (NB + 1) / 2)   // 528, column-major: t = bj*(bj+1)/2 + bi
#define NLAB 512
#define BCAP 64
#define GCTAS 148

// ---------------- device globals ----------------
__device__ __align__(16) __nv_bfloat16  g_normh[N * D]; // rows pre-swizzled: chunk c at c^(row&7)
__device__ int      g_lab[N];
__device__ float    g_tot[N];
__device__ float    g_loss_f;
__device__ unsigned g_cnt;
__device__ unsigned g_done;
__device__ int      g_bstart[NLAB + 1];
__device__ int      g_bidx[N];

// ---------------- smem layout for k_gemm ----------------
#define SMEM_A0   0
#define SMEM_A1   65536
#define SMEM_B    131072
#define SMEM_LABI 196608
#define SMEM_LABJ 197120
#define SMEM_MBA0 197632
#define SMEM_MBA1 197640
#define SMEM_MBB  197648
#define SMEM_GT   197760

__device__ __forceinline__ uint32_t smem_u32(const void* p) {
    uint32_t a;
    asm("{ .reg .u64 t; cvta.to.shared.u64 t, %1; cvt.u32.u64 %0, t; }" : "=r"(a) : "l"(p));
    return a;
}
#define MBAR_INIT(mb, c)  asm volatile("mbarrier.init.shared.b64 [%0], %1;" :: "r"(mb), "r"(c) : "memory")
#define MBAR_EXPECT(mb, tx) asm volatile("mbarrier.arrive.expect_tx.shared.b64 _, [%0], %1;" :: "r"(mb), "r"(tx) : "memory")
#define BULK_LD(dst, src, sz, mb) \
    asm volatile("cp.async.bulk.shared::cta.global.mbarrier::complete_tx::bytes [%0], [%1], %2, [%3];" \
        :: "r"(dst), "l"(src), "r"(sz), "r"(mb) : "memory")

__device__ __forceinline__ void mbar_wait(uint32_t mb, uint32_t parity) {
    uint32_t done;
    asm volatile("{ .reg .pred p; mbarrier.try_wait.parity.acquire.cta.shared::cta.b64 p, [%1], %2; selp.b32 %0, 1, 0, p; }"
                 : "=r"(done) : "r"(mb), "r"(parity) : "memory");
    if (!done) {
        asm volatile("{ .reg .pred P1; W%=: mbarrier.try_wait.parity.acquire.cta.shared::cta.b64 P1, [%0], %1, 0x989680; @P1 bra.uni DN%=; bra.uni W%=; DN%=: }"
                     :: "r"(mb), "r"(parity) : "memory");
    }
}

#define LDSM4(r, a) \
    asm volatile("ldmatrix.sync.aligned.m8n8.x4.shared.b16 {%0,%1,%2,%3}, [%4];" \
        : "=r"((r)[0]), "=r"((r)[1]), "=r"((r)[2]), "=r"((r)[3]) : "r"(a))
#define LDSM4T(r, a) \
    asm volatile("ldmatrix.sync.aligned.m8n8.x4.trans.shared.b16 {%0,%1,%2,%3}, [%4];" \
        : "=r"((r)[0]), "=r"((r)[1]), "=r"((r)[2]), "=r"((r)[3]) : "r"(a))
#define MMA16816(d, a, b0_, b1_) \
    asm volatile("mma.sync.aligned.m16n8k16.row.col.f32.bf16.bf16.f32 " \
        "{%0,%1,%2,%3}, {%4,%5,%6,%7}, {%8,%9}, {%0,%1,%2,%3};" \
        : "+f"((d)[0]), "+f"((d)[1]), "+f"((d)[2]), "+f"((d)[3]) \
        : "r"((a)[0]), "r"((a)[1]), "r"((a)[2]), "r"((a)[3]), "r"(b0_), "r"(b1_))

// ---------------- kernels ----------------
__global__ void k_norm(const float* __restrict__ x) {
    int row = blockIdx.x;
    int t = threadIdx.x;  // 256 == D
    float v = x[row * D + t];
    float sq = v * v;
    #pragma unroll
    for (int o = 16; o > 0; o >>= 1) sq += __shfl_down_sync(0xffffffffu, sq, o);
    __shared__ float wsum[8];
    if ((t & 31) == 0) wsum[t >> 5] = sq;
    __syncthreads();
    float s = 0.f;
    #pragma unroll
    for (int w = 0; w < 8; w++) s += wsum[w];
    float denom = fmaxf(sqrtf(s), 1e-12f);
    int c = t >> 3;
    int cs = c ^ (row & 7);
    g_normh[row * D + cs * 8 + (t & 7)] = __float2bfloat16_rn(v / denom);
    if (t == 0) g_tot[row] = 0.f;
}

// Labels: int64/int32 sniff + convert + bucket (histogram/scan/scatter). One block.
__global__ void k_bucket(const void* __restrict__ labels) {
    __shared__ int s_nz;
    __shared__ int cnt[NLAB];
    __shared__ int buf[2][NLAB];
    int t = threadIdx.x;   // 512
    if (t == 0) { s_nz = 0; g_loss_f = 0.f; g_cnt = 0u; g_done = 0u; }
    cnt[t] = 0;
    __syncthreads();
    const int* l32 = (const int*)labels;
    int nz = 0;
    #pragma unroll
    for (int i = t; i < N / 2; i += NLAB) nz |= (l32[2 * i + 1] != 0);
    if (nz) atomicOr(&s_nz, 1);
    __syncthreads();
    const bool is64 = (s_nz == 0);
    #pragma unroll
    for (int r = t; r < N; r += NLAB) {
        int lv = is64 ? (int)((const long long*)labels)[r] : l32[r];
        g_lab[r] = lv;
        atomicAdd(&cnt[lv], 1);
    }
    __syncthreads();
    buf[0][t] = cnt[t];
    __syncthreads();
    int src = 0;
    #pragma unroll
    for (int o = 1; o < NLAB; o <<= 1) {
        int v = buf[src][t];
        if (t >= o) v += buf[src][t - o];
        buf[1 - src][t] = v;
        src = 1 - src;
        __syncthreads();
    }
    int excl = buf[src][t] - cnt[t];
    g_bstart[t] = excl;
    if (t == NLAB - 1) g_bstart[NLAB] = N;
    cnt[t] = excl;
    __syncthreads();
    #pragma unroll
    for (int r = t; r < N; r += NLAB) {
        int p = atomicAdd(&cnt[g_lab[r]], 1);
        g_bidx[p] = r;
    }
}

__device__ __forceinline__ void tile_decode(int t, int& bi, int& bj) {
    int b = (int)((sqrtf(8.f * (float)t + 1.f) - 1.f) * 0.5f);
    while ((b + 1) * (b + 2) / 2 <= t) b++;
    while (b * (b + 1) / 2 > t) b--;
    bj = b;
    bi = t - b * (b + 1) / 2;
}

// Persistent bf16 mma.sync GEMM over upper-triangle tiles, column-major order.
// B (bj block) cached per column; A (bi block) double-buffered w/ prefetch.
// 512 threads: 16 warps, 4x4, warp tile 32x32. Epilogue: f16x2 EX2 tot sums.
__global__ __launch_bounds__(512, 1) void k_gemm() {
    extern __shared__ char smem[];
    const int tid = threadIdx.x, wid = tid >> 5, l = tid & 31;
    const int wm = wid & 3, wn = wid >> 2;
    const uint32_t sb = smem_u32(smem);
    int* labi = (int*)(smem + SMEM_LABI);
    int* labj = (int*)(smem + SMEM_LABJ);

    if (tid == 0) {
        MBAR_INIT(sb + SMEM_MBA0, 1);
        MBAR_INIT(sb + SMEM_MBA1, 1);
        MBAR_INIT(sb + SMEM_MBB, 1);
    }
    __syncthreads();

    const int s = (int)(((long)blockIdx.x * NTILES) / GCTAS);
    const int e = (int)(((long)(blockIdx.x + 1) * NTILES) / GCTAS);

    int aph[2] = {0, 0}, bph = 0;
    int ab = 0;
    bool a_issued = false;
    int prev_bj = -1;

    const half2 SC = __float2half2_rn(2.8853900817779268f);   // 2*log2(e)

    for (int t = s; t < e; t++) {
        int bi, bj;
        tile_decode(t, bi, bj);
        const bool diag = (bi == bj);
        const bool newcol = (bj != prev_bj);
        prev_bj = bj;
        const int iBase = bi * 128;
        const int jBase = bj * 128;

        __syncthreads();   // prev epilogue done (labels free), prev compute done (smem free)

        if (tid == 0) {
            if (newcol) {
                MBAR_EXPECT(sb + SMEM_MBB, 65536u);
                #pragma unroll
                for (int q = 0; q < 8; q++)
                    BULK_LD(sb + SMEM_B + q * 8192,
                            (const char*)&g_normh[(size_t)jBase * D] + q * 8192, 8192u, sb + SMEM_MBB);
            }
            if (!diag && !a_issued) {
                uint32_t mba = sb + (ab ? SMEM_MBA1 : SMEM_MBA0);
                uint32_t abuf = (ab ? SMEM_A1 : SMEM_A0);
                MBAR_EXPECT(mba, 65536u);
                #pragma unroll
                for (int q = 0; q < 8; q++)
                    BULK_LD(sb + abuf + q * 8192,
                            (const char*)&g_normh[(size_t)iBase * D] + q * 8192, 8192u, mba);
            }
        }
        if (tid < 128) labi[tid] = g_lab[iBase + tid];
        else if (tid < 256) labj[tid - 128] = g_lab[jBase + tid - 128];

        if (newcol) { mbar_wait(sb + SMEM_MBB, bph); bph ^= 1; }
        if (!diag)  { mbar_wait(sb + (ab ? SMEM_MBA1 : SMEM_MBA0), aph[ab]); aph[ab] ^= 1; }
        __syncthreads();   // labels + tile data visible to all

        // ---- compute ----
        float acc[2][4][4];
        #pragma unroll
        for (int mt = 0; mt < 2; mt++)
            #pragma unroll
            for (int nt = 0; nt < 4; nt++)
                #pragma unroll
                for (int ee = 0; ee < 4; ee++) acc[mt][nt][ee] = 0.f;

        const uint32_t aspace = diag ? (uint32_t)SMEM_B : (ab ? (uint32_t)SMEM_A1 : (uint32_t)SMEM_A0);
        const int row_a = wm * 32 + (l & 15);
        const uint32_t abase = sb + aspace + (uint32_t)row_a * 512;
        const int rxa = row_a & 7;
        const int hia = (l >> 4);
        const int row_b = wn * 32 + (l & 7) + ((l & 16) ? 8 : 0);
        const uint32_t bbase = sb + SMEM_B + (uint32_t)row_b * 512;
        const int rxb = row_b & 7;
        const int hib = (l >> 3) & 1;

        #pragma unroll
        for (int ks = 0; ks < 16; ks++) {
            const uint32_t ka = (uint32_t)(((ks * 2 + hia) ^ rxa) << 4);
            const uint32_t kb = (uint32_t)(((ks * 2 + hib) ^ rxb) << 4);
            uint32_t A0[4], A1[4];
            LDSM4(A0, abase + ka);
            LDSM4(A1, abase + 8192 + ka);
            #pragma unroll
            for (int p = 0; p < 2; p++) {
                uint32_t Bt[4];
                LDSM4T(Bt, bbase + (uint32_t)p * 8192 + kb);
                MMA16816(acc[0][2 * p],     A0, Bt[0], Bt[1]);
                MMA16816(acc[0][2 * p + 1], A0, Bt[2], Bt[3]);
                MMA16816(acc[1][2 * p],     A1, Bt[0], Bt[1]);
                MMA16816(acc[1][2 * p + 1], A1, Bt[2], Bt[3]);
            }
        }
        __syncthreads();   // all warps done reading smem tiles

        // ---- prefetch next tile's A (overlaps epilogue) ----
        a_issued = false;
        if (t + 1 < e) {
            int bi2, bj2;
            tile_decode(t + 1, bi2, bj2);
            if (bi2 != bj2) {
                const int nb = diag ? ab : (ab ^ 1);
                if (tid == 0) {
                    uint32_t mba = sb + (nb ? SMEM_MBA1 : SMEM_MBA0);
                    uint32_t abuf = (nb ? SMEM_A1 : SMEM_A0);
                    MBAR_EXPECT(mba, 65536u);
                    #pragma unroll
                    for (int q = 0; q < 8; q++)
                        BULK_LD(sb + abuf + q * 8192,
                                (const char*)&g_normh[(size_t)(bi2 * 128) * D] + q * 8192, 8192u, mba);
                }
                ab = nb;
                a_issued = true;
            }
        }

        // ---- epilogue: exp(2s) via f16x2 EX2, row + column tot sums ----
        half2 ctot2[4];
        #pragma unroll
        for (int nt = 0; nt < 4; nt++) ctot2[nt] = __float2half2_rn(0.f);

        half2 cidx[4];
        if (diag) {
            #pragma unroll
            for (int nt = 0; nt < 4; nt++) {
                float c0 = (float)(wn * 32 + nt * 8 + (l & 3) * 2);
                cidx[nt] = __floats2half2_rn(c0, c0 + 1.0f);
            }
        }

        #pragma unroll
        for (int mt = 0; mt < 2; mt++) {
            #pragma unroll
            for (int half_ = 0; half_ < 2; half_++) {
                const int row_local = wm * 32 + mt * 16 + half_ * 8 + (l >> 2);
                const int gi = iBase + row_local;
                half2 t2 = __float2half2_rn(0.f);
                if (diag) {
                    const half2 r2 = __float2half2_rn((float)row_local);
                    #pragma unroll
                    for (int nt = 0; nt < 4; nt++) {
                        half2 h = __floats2half2_rn(acc[mt][nt][half_ * 2], acc[mt][nt][half_ * 2 + 1]);
                        half2 ex = h2exp2(__hmul2(h, SC));
                        half2 eq = __heq2(cidx[nt], r2);
                        ex = __hsub2(ex, __hmul2(ex, eq));
                        t2 = __hadd2(t2, ex);
                        ctot2[nt] = __hadd2(ctot2[nt], ex);
                    }
                } else {
                    #pragma unroll
                    for (int nt = 0; nt < 4; nt++) {
                        half2 h = __floats2half2_rn(acc[mt][nt][half_ * 2], acc[mt][nt][half_ * 2 + 1]);
                        half2 ex = h2exp2(__hmul2(h, SC));
                        t2 = __hadd2(t2, ex);
                        ctot2[nt] = __hadd2(ctot2[nt], ex);
                    }
                }
                float2 f = __half22float2(t2);
                float tt = f.x + f.y;
                tt += __shfl_xor_sync(0xffffffffu, tt, 1);
                tt += __shfl_xor_sync(0xffffffffu, tt, 2);
                if ((l & 3) == 0) atomicAdd(&g_tot[gi], tt);
            }
        }
        if (!diag) {
            #pragma unroll
            for (int nt = 0; nt < 4; nt++) {
                uint32_t v = *(uint32_t*)&ctot2[nt];
                #pragma unroll
                for (int m = 4; m <= 16; m <<= 1) {
                    uint32_t o = __shfl_xor_sync(0xffffffffu, v, m);
                    half2 hv = *(half2*)&v, ho = *(half2*)&o;
                    hv = __hadd2(hv, ho);
                    v = *(uint32_t*)&hv;
                }
                if (l < 4) {
                    float2 fc = __half22float2(*(half2*)&v);
                    int c0 = wn * 32 + nt * 8 + l * 2;
                    atomicAdd(&g_tot[jBase + c0], fc.x);
                    atomicAdd(&g_tot[jBase + c0 + 1], fc.y);
                }
            }
        }
    }
}

// ---------------- loss: one block per label bucket ----------------
__device__ __forceinline__ void tri_decode(int p, int n, int& a, int& b) {
    a = 0;
    int rem = p;
    while (rem >= n - 1 - a) { rem -= (n - 1 - a); a++; }
    b = a + 1 + rem;
}

__device__ __forceinline__ float warp_dot_smem(const uint4* ra, const uint4* rb, int l) {
    uint4 xa = ra[l], xb = rb[l];
    float s = 0.f;
    const uint32_t* pa = (const uint32_t*)&xa;
    const uint32_t* pb = (const uint32_t*)&xb;
    #pragma unroll
    for (int q = 0; q < 4; q++) {
        float2 fa = __bfloat1622float2(*(const __nv_bfloat162*)&pa[q]);
        float2 fb = __bfloat1622float2(*(const __nv_bfloat162*)&pb[q]);
        s += fa.x * fb.x + fa.y * fb.y;
    }
    #pragma unroll
    for (int o = 16; o > 0; o >>= 1) s += __shfl_xor_sync(0xffffffffu, s, o);
    return s;
}

__device__ __forceinline__ float warp_dot_gmem(int ga, int gb, int l) {
    const uint4* pa = (const uint4*)&g_normh[(size_t)ga * D + (size_t)((l ^ (ga & 7)) * 8)];
    const uint4* pb = (const uint4*)&g_normh[(size_t)gb * D + (size_t)((l ^ (gb & 7)) * 8)];
    uint4 xa = *pa, xb = *pb;
    float s = 0.f;
    const uint32_t* qa = (const uint32_t*)&xa;
    const uint32_t* qb = (const uint32_t*)&xb;
    #pragma unroll
    for (int q = 0; q < 4; q++) {
        float2 fa = __bfloat1622float2(*(const __nv_bfloat162*)&qa[q]);
        float2 fb = __bfloat1622float2(*(const __nv_bfloat162*)&qb[q]);
        s += fa.x * fb.x + fa.y * fb.y;
    }
    #pragma unroll
    for (int o = 16; o > 0; o >>= 1) s += __shfl_xor_sync(0xffffffffu, s, o);
    return s;
}

#define LSM_ROWS 0
#define LSM_SMAT (BCAP * 32 * 16)
#define LSM_NEG  (LSM_SMAT + BCAP * (BCAP + 1) * 4)
#define LSM_IDX  (LSM_NEG + BCAP * 4)
#define LSM_TOTAL (LSM_IDX + BCAP * 4 + 64)

__global__ __launch_bounds__(128) void k_loss4(float* __restrict__ out) {
    extern __shared__ char sm[];
    uint4* rows4 = (uint4*)(sm + LSM_ROWS);
    float* smat  = (float*)(sm + LSM_SMAT);
    float* sneg  = (float*)(sm + LSM_NEG);
    int*   sidx  = (int*)(sm + LSM_IDX);

    const int L = blockIdx.x;
    const int tid = threadIdx.x, wid = tid >> 5, l = tid & 31;
    const int base = g_bstart[L];
    const int n = g_bstart[L + 1] - base;
    float lsum = 0.f;
    unsigned lcnt = 0;

    if (n >= 2 && n <= BCAP) {
        if (tid < n) sidx[tid] = g_bidx[base + tid];
        __syncthreads();
        for (int idx = tid; idx < n * 32; idx += 128) {
            int a = idx >> 5, c = idx & 31;
            int gr = sidx[a];
            rows4[a * 32 + c] = *(const uint4*)&g_normh[(size_t)gr * D + (size_t)((c ^ (gr & 7)) * 8)];
        }
        __syncthreads();
        const int np = n * (n - 1) / 2;
        for (int p = wid; p < np; p += 4) {
            int a, b;
            tri_decode(p, n, a, b);
            float s = warp_dot_smem(&rows4[a * 32], &rows4[b * 32], l);
            if (l == 0) {
                smat[a * (BCAP + 1) + b] = s;
                smat[b * (BCAP + 1) + a] = s;
            }
        }
        __syncthreads();
        if (tid < n) {
            float pos = 0.f;
            for (int b = 0; b < n; b++)
                if (b != tid) pos += __expf(2.0f * smat[tid * (BCAP + 1) + b]);
            sneg[tid] = g_tot[sidx[tid]] - pos;
        }
        __syncthreads();
        for (int p = tid; p < np; p += 128) {
            int a, b;
            tri_decode(p, n, a, b);
            float s = smat[a * (BCAP + 1) + b];
            float e = __expf(2.0f * s);
            lsum += logf(e + sneg[a]) + logf(e + sneg[b]) - 4.0f * s;
        }
        lcnt = (tid == 0) ? (unsigned)(2 * np) : 0u;
    } else if (n > BCAP) {
        for (int a = wid; a < n; a += 4) {
            int ga = g_bidx[base + a];
            float pos = 0.f;
            for (int b = 0; b < n; b++) {
                if (b == a) continue;
                float s = warp_dot_gmem(ga, g_bidx[base + b], l);
                pos += __expf(2.0f * s);
            }
            float neg = g_tot[ga] - pos;
            float part = 0.f;
            for (int b = 0; b < n; b++) {
                if (b == a) continue;
                float s = warp_dot_gmem(ga, g_bidx[base + b], l);
                float e = __expf(2.0f * s);
                part += logf(e + neg) - 2.0f * s;
            }
            if (l == 0) { lsum += part; lcnt += (unsigned)(n - 1); }
        }
    }

    #pragma unroll
    for (int o = 16; o > 0; o >>= 1) lsum += __shfl_down_sync(0xffffffffu, lsum, o);
    __shared__ float sred[4];
    __shared__ unsigned scnt[4];
    unsigned wcnt = lcnt;
    #pragma unroll
    for (int o = 16; o > 0; o >>= 1) wcnt += __shfl_down_sync(0xffffffffu, wcnt, o);
    if (l == 0) { sred[wid] = lsum; scnt[wid] = wcnt; }
    __syncthreads();
    if (tid == 0) {
        float Ls = sred[0] + sred[1] + sred[2] + sred[3];
        unsigned C = scnt[0] + scnt[1] + scnt[2] + scnt[3];
        if (Ls != 0.f) atomicAdd(&g_loss_f, Ls);
        if (C) atomicAdd(&g_cnt, C);
        __threadfence();
        unsigned d = atomicAdd(&g_done, 1u);
        if (d == gridDim.x - 1) {
            float total = atomicAdd(&g_loss_f, 0.f);
            unsigned cc = atomicAdd(&g_cnt, 0u);
            out[0] = total / (float)cc;
        }
    }
}

// ---------------- launch ----------------
extern "C" void kernel_launch(void* const* d_in, const int* in_sizes, int n_in,
                              void* d_out, int out_size) {
    const float* x = (const float*)d_in[0];
    const void* labels = d_in[1];

    static bool attr_done = false;
    if (!attr_done) {
        cudaFuncSetAttribute(k_gemm, cudaFuncAttributeMaxDynamicSharedMemorySize, SMEM_GT);
        cudaFuncSetAttribute(k_loss4, cudaFuncAttributeMaxDynamicSharedMemorySize, LSM_TOTAL);
        attr_done = true;
    }

    k_norm<<<N, 256>>>(x);
    k_bucket<<<1, NLAB>>>(labels);
    k_gemm<<<GCTAS, 512, SMEM_GT>>>();
    k_loss4<<<NLAB, 128, LSM_TOTAL>>>((float*)d_out);
}